// round 7
// baseline (speedup 1.0000x reference)
#include <cuda_runtime.h>
#include <cstdint>
#include <cstddef>

#define NU_N 100000
#define NI_N 100000
#define NN 100000
#define NEDGE 600000
#define D 128
#define NBLK 98            // ceil(NN / 1024)

// ---------------- scratch (static device globals; 16B-aligned) ----------------
__device__ __align__(16) float g_WhA[(size_t)NN * D];
__device__ __align__(16) float g_WhB[(size_t)NN * D];
__device__ __align__(16) int g_deg[3 * NN];
__device__ __align__(16) int g_off[3 * (NN + 1)];
__device__ __align__(16) int g_bsum[3 * 128];
__device__ __align__(16) int g_cur[3 * NN];
__device__ __align__(16) int g_esrc[3 * NEDGE];
// W fragments, hi/lo tf32, mma.sync m16n8k8 B-layout: [etype][kc][nb][lane]{bh0,bh1,bl0,bl1}
__device__ __align__(16) uint4 g_Wfrag[3 * 256 * 32];

// ---------------- tf32 helpers (base sm_100; no 'a' features) ----------------
__device__ __forceinline__ uint32_t cvt_tf32(float f) {
    uint32_t r;
    asm("cvt.rna.tf32.f32 %0, %1;" : "=r"(r) : "f"(f));
    return r;
}
__device__ __forceinline__ void split_tf32(float v, uint32_t& hi, uint32_t& lo) {
    hi = cvt_tf32(v);
    lo = cvt_tf32(v - __uint_as_float(hi));
}
__device__ __forceinline__ void mma_tf32(float* c, const uint32_t* a,
                                         uint32_t b0, uint32_t b1) {
    asm volatile(
        "mma.sync.aligned.m16n8k8.row.col.f32.tf32.tf32.f32 "
        "{%0,%1,%2,%3}, {%4,%5,%6,%7}, {%8,%9}, {%0,%1,%2,%3};"
        : "+f"(c[0]), "+f"(c[1]), "+f"(c[2]), "+f"(c[3])
        : "r"(a[0]), "r"(a[1]), "r"(a[2]), "r"(a[3]), "r"(b0), "r"(b1));
}

// ---------------- W fragment prep: W[128][128] -> hi/lo frag order -------------
// grid (16 kc, 16 nb, 3 etype), 32 threads. b0:(k=lc, n=lr)  b1:(k=lc+4, n=lr)
__global__ void __launch_bounds__(32)
w_prep(const float* __restrict__ W0, const float* __restrict__ W1,
       const float* __restrict__ W2, uint4* __restrict__ frags) {
    int kc = blockIdx.x, nb = blockIdx.y, et = blockIdx.z;
    const float* W = (et == 0) ? W0 : (et == 1) ? W1 : W2;
    int l = threadIdx.x;
    int lr = l >> 2, lc = l & 3;
    int k0 = kc * 8 + lc;
    int nn = nb * 8 + lr;
    float b0 = __ldg(W + (size_t)k0 * D + nn);
    float b1 = __ldg(W + (size_t)(k0 + 4) * D + nn);
    uint32_t h0, l0, h1, l1;
    split_tf32(b0, h0, l0);
    split_tf32(b1, h1, l1);
    frags[((size_t)et * 256 + kc * 16 + nb) * 32 + l] = make_uint4(h0, h1, l0, l1);
}

// ---------------- tensor-core GEMM: out[n,128] = A[n,128] @ W + b --------------
// 256 threads = 8 warps. warp w: rows [blk*128 + 32*(w&3), +32), cols [64*(w>>2), +64).
// 3xTF32: D = Ah*Bh + Al*Bh + Ah*Bl.
__global__ void __launch_bounds__(256)
gemm_mma(const float* __restrict__ A, const uint4* __restrict__ frags,
         const float* __restrict__ bias, float* __restrict__ out, int n) {
    int tid = threadIdx.x, w = tid >> 5, l = tid & 31;
    int mw = w & 3, nw = w >> 2;
    int rowBase = blockIdx.x * 128 + mw * 32;
    int lr = l >> 2, lc = l & 3;

    float c[2][8][4];
#pragma unroll
    for (int mt = 0; mt < 2; ++mt)
#pragma unroll
        for (int nb = 0; nb < 8; ++nb)
#pragma unroll
            for (int j = 0; j < 4; ++j) c[mt][nb][j] = 0.f;

#pragma unroll 1
    for (int kc = 0; kc < 16; ++kc) {
        uint32_t ah[2][4], al[2][4];
        int col = kc * 8 + lc;
#pragma unroll
        for (int mt = 0; mt < 2; ++mt) {
            int r0 = rowBase + mt * 16 + lr;
            int r1 = r0 + 8;
            if (r0 >= n) r0 = n - 1;               // clamp loads; stores guarded
            if (r1 >= n) r1 = n - 1;
            float a0 = __ldg(A + (size_t)r0 * D + col);
            float a1 = __ldg(A + (size_t)r1 * D + col);
            float a2 = __ldg(A + (size_t)r0 * D + col + 4);
            float a3 = __ldg(A + (size_t)r1 * D + col + 4);
            split_tf32(a0, ah[mt][0], al[mt][0]);
            split_tf32(a1, ah[mt][1], al[mt][1]);
            split_tf32(a2, ah[mt][2], al[mt][2]);
            split_tf32(a3, ah[mt][3], al[mt][3]);
        }
#pragma unroll
        for (int nb = 0; nb < 8; ++nb) {
            uint4 bf = __ldg(frags + ((size_t)kc * 16 + nw * 8 + nb) * 32 + l);
#pragma unroll
            for (int mt = 0; mt < 2; ++mt) {
                mma_tf32(c[mt][nb], ah[mt], bf.x, bf.y);   // Ah*Bh
                mma_tf32(c[mt][nb], al[mt], bf.x, bf.y);   // Al*Bh
                mma_tf32(c[mt][nb], ah[mt], bf.z, bf.w);   // Ah*Bl
            }
        }
    }

    // epilogue: c0/c1 -> (row, col..col+1), c2/c3 -> (row+8, ...)
#pragma unroll
    for (int nb = 0; nb < 8; ++nb) {
        int col = nw * 64 + nb * 8 + lc * 2;
        float2 bv = *(const float2*)(bias + col);
#pragma unroll
        for (int mt = 0; mt < 2; ++mt) {
            int r0 = rowBase + mt * 16 + lr;
            if (r0 < n)
                *(float2*)(out + (size_t)r0 * D + col) =
                    make_float2(c[mt][nb][0] + bv.x, c[mt][nb][1] + bv.y);
            if (r0 + 8 < n)
                *(float2*)(out + (size_t)(r0 + 8) * D + col) =
                    make_float2(c[mt][nb][2] + bv.x, c[mt][nb][3] + bv.y);
        }
    }
}

// ---------------- CSR build (unchanged from passing R4) ----------------
__global__ void __launch_bounds__(256)
hist3(const int* __restrict__ d0, const int* __restrict__ d1,
      const int* __restrict__ d2, int* __restrict__ deg) {
    int e = blockIdx.x * 256 + threadIdx.x;
    if (e >= NEDGE) return;
    int y = blockIdx.y;
    const int* d = (y == 0) ? d0 : (y == 1) ? d1 : d2;
    atomicAdd(deg + y * NN + __ldg(d + e), 1);
}

__global__ void __launch_bounds__(256)
scan1(const int* __restrict__ deg, int* __restrict__ off, int* __restrict__ bsum) {
    int y = blockIdx.y;
    const int* d = deg + y * NN;
    int* o = off + y * (NN + 1);
    int tid = threadIdx.x, lane = tid & 31, warp = tid >> 5;
    int base = blockIdx.x * 1024 + tid * 4;

    int v0 = (base + 0 < NN) ? d[base + 0] : 0;
    int v1 = (base + 1 < NN) ? d[base + 1] : 0;
    int v2 = (base + 2 < NN) ? d[base + 2] : 0;
    int v3 = (base + 3 < NN) ? d[base + 3] : 0;
    int tsum = v0 + v1 + v2 + v3;

    int x = tsum;
#pragma unroll
    for (int ofs = 1; ofs < 32; ofs <<= 1) {
        int t = __shfl_up_sync(0xffffffffu, x, ofs);
        if (lane >= ofs) x += t;
    }
    __shared__ int ws[8];
    if (lane == 31) ws[warp] = x;
    __syncthreads();
    if (tid == 0) {
        int run = 0;
#pragma unroll
        for (int i = 0; i < 8; ++i) { int t = ws[i]; ws[i] = run; run += t; }
        bsum[y * 128 + blockIdx.x] = run;
    }
    __syncthreads();

    int excl = ws[warp] + x - tsum;
    if (base + 0 < NN) o[base + 0] = excl;
    if (base + 1 < NN) o[base + 1] = excl + v0;
    if (base + 2 < NN) o[base + 2] = excl + v0 + v1;
    if (base + 3 < NN) o[base + 3] = excl + v0 + v1 + v2;
}

__global__ void __launch_bounds__(32)
scan2(int* __restrict__ bsum) {
    if (threadIdx.x == 0) {
        int* b = bsum + blockIdx.y * 128;
        int run = 0;
        for (int i = 0; i < NBLK; ++i) { int t = b[i]; b[i] = run; run += t; }
    }
}

__global__ void __launch_bounds__(256)
scan3(int* __restrict__ off, const int* __restrict__ bsum, int* __restrict__ cur) {
    int y = blockIdx.y;
    int* o = off + y * (NN + 1);
    int* c = cur + y * NN;
    int add = bsum[y * 128 + blockIdx.x];
    int base = blockIdx.x * 1024 + threadIdx.x * 4;
#pragma unroll
    for (int i = 0; i < 4; ++i) {
        int idx = base + i;
        if (idx < NN) { int v = o[idx] + add; o[idx] = v; c[idx] = v; }
    }
    if (blockIdx.x == 0 && threadIdx.x == 0) o[NN] = NEDGE;
}

__global__ void __launch_bounds__(256)
fill3(const int* __restrict__ s0, const int* __restrict__ d0,
      const int* __restrict__ s1, const int* __restrict__ d1,
      const int* __restrict__ s2, const int* __restrict__ d2,
      int* __restrict__ cur, int* __restrict__ esrc) {
    int e = blockIdx.x * 256 + threadIdx.x;
    if (e >= NEDGE) return;
    int y = blockIdx.y;
    const int* s = (y == 0) ? s0 : (y == 1) ? s1 : s2;
    const int* d = (y == 0) ? d0 : (y == 1) ? d1 : d2;
    int dn = __ldg(d + e);
    int pos = atomicAdd(cur + y * NN + dn, 1);
    esrc[y * NEDGE + pos] = __ldg(s + e);
}

// ---------------- pull aggregation (unchanged from passing R4) ----------------
__device__ __forceinline__ void acc4(float4& acc, const float4& a) {
    acc.x += a.x; acc.y += a.y; acc.z += a.z; acc.w += a.w;
}

__device__ __forceinline__ float4 pull_seg(const float* __restrict__ Wh,
                                           const int* __restrict__ esrc,
                                           int s0, int s1, int lane) {
    float4 acc = make_float4(0.f, 0.f, 0.f, 0.f);
    int e = s0;
    for (; e + 4 <= s1; e += 4) {
        int i0 = __ldg(esrc + e + 0);
        int i1 = __ldg(esrc + e + 1);
        int i2 = __ldg(esrc + e + 2);
        int i3 = __ldg(esrc + e + 3);
        float4 a = ((const float4*)(Wh + (size_t)i0 * D))[lane];
        float4 b = ((const float4*)(Wh + (size_t)i1 * D))[lane];
        float4 c = ((const float4*)(Wh + (size_t)i2 * D))[lane];
        float4 dd = ((const float4*)(Wh + (size_t)i3 * D))[lane];
        acc4(acc, a); acc4(acc, b); acc4(acc, c); acc4(acc, dd);
    }
    for (; e < s1; ++e) {
        int i = __ldg(esrc + e);
        float4 a = ((const float4*)(Wh + (size_t)i * D))[lane];
        acc4(acc, a);
    }
    return acc;
}

__global__ void __launch_bounds__(256)
pull_item(const float* __restrict__ Wh, const int* __restrict__ off,
          const int* __restrict__ esrc, float* __restrict__ out) {
    int g = blockIdx.x * 256 + threadIdx.x;
    int node = g >> 5, lane = g & 31;
    if (node >= NN) return;
    int s0 = __ldg(off + node), s1 = __ldg(off + node + 1);
    float4 acc = pull_seg(Wh, esrc, s0, s1, lane);
    float r = (s1 > s0) ? 1.f / (float)(s1 - s0) : 0.f;
    ((float4*)(out + (size_t)node * D))[lane] =
        make_float4(acc.x * r, acc.y * r, acc.z * r, acc.w * r);
}

__global__ void __launch_bounds__(256)
pull_user(const float* __restrict__ WhIU, const int* __restrict__ offIU,
          const int* __restrict__ esrcIU,
          const float* __restrict__ WhUU, const int* __restrict__ offUU,
          const int* __restrict__ esrcUU, float* __restrict__ out) {
    int g = blockIdx.x * 256 + threadIdx.x;
    int node = g >> 5, lane = g & 31;
    if (node >= NN) return;
    int a0 = __ldg(offIU + node), a1 = __ldg(offIU + node + 1);
    int b0 = __ldg(offUU + node), b1 = __ldg(offUU + node + 1);
    float4 ai = pull_seg(WhIU, esrcIU, a0, a1, lane);
    float4 au = pull_seg(WhUU, esrcUU, b0, b1, lane);
    float ri = (a1 > a0) ? 1.f / (float)(a1 - a0) : 0.f;
    float ru = (b1 > b0) ? 1.f / (float)(b1 - b0) : 0.f;
    ((float4*)(out + (size_t)node * D))[lane] =
        make_float4(ai.x * ri + au.x * ru, ai.y * ri + au.y * ru,
                    ai.z * ri + au.z * ru, ai.w * ri + au.w * ru);
}

// ---------------- launch ----------------
extern "C" void kernel_launch(void* const* d_in, const int* in_sizes, int n_in,
                              void* d_out, int out_size) {
    const float* feat_user = (const float*)d_in[0];
    const float* feat_item = (const float*)d_in[1];
    const float* W_ui = (const float*)d_in[2];
    const float* b_ui = (const float*)d_in[3];
    const float* W_iu = (const float*)d_in[4];
    const float* b_iu = (const float*)d_in[5];
    const float* W_uu = (const float*)d_in[6];
    const float* b_uu = (const float*)d_in[7];
    const int* src_ui = (const int*)d_in[8];
    const int* dst_ui = (const int*)d_in[9];
    const int* src_iu = (const int*)d_in[10];
    const int* dst_iu = (const int*)d_in[11];
    const int* src_uu = (const int*)d_in[12];
    const int* dst_uu = (const int*)d_in[13];
    float* out = (float*)d_out;

    void *pWhA, *pWhB, *pDeg, *pOff, *pBsum, *pCur, *pEsrc, *pWf;
    cudaGetSymbolAddress(&pWhA, g_WhA);
    cudaGetSymbolAddress(&pWhB, g_WhB);
    cudaGetSymbolAddress(&pDeg, g_deg);
    cudaGetSymbolAddress(&pOff, g_off);
    cudaGetSymbolAddress(&pBsum, g_bsum);
    cudaGetSymbolAddress(&pCur, g_cur);
    cudaGetSymbolAddress(&pEsrc, g_esrc);
    cudaGetSymbolAddress(&pWf, g_Wfrag);

    float* WhA = (float*)pWhA;
    float* WhB = (float*)pWhB;
    int* deg = (int*)pDeg;
    int* off = (int*)pOff;
    int* bsum = (int*)pBsum;
    int* cur = (int*)pCur;
    int* esrc = (int*)pEsrc;
    uint4* wfrag = (uint4*)pWf;

    // ---- CSR build (etype order: 0=ui, 1=iu, 2=uu) ----
    cudaMemsetAsync(deg, 0, 3 * NN * sizeof(int));
    dim3 eGrid((NEDGE + 255) / 256, 3);
    hist3<<<eGrid, 256>>>(dst_ui, dst_iu, dst_uu, deg);
    dim3 sGrid(NBLK, 3);
    scan1<<<sGrid, 256>>>(deg, off, bsum);
    scan2<<<dim3(1, 3), 32>>>(bsum);
    scan3<<<sGrid, 256>>>(off, bsum, cur);
    fill3<<<eGrid, 256>>>(src_ui, dst_ui, src_iu, dst_iu, src_uu, dst_uu,
                          cur, esrc);

    // ---- W fragment prep (all 3 etypes) ----
    w_prep<<<dim3(16, 16, 3), 32>>>(W_ui, W_iu, W_uu, wfrag);

    int gGrid = (NN + 127) / 128;   // 782
    int pGrid = (NN * 32 + 255) / 256;

    // etype ui: project users, pull into item output half
    gemm_mma<<<gGrid, 256>>>(feat_user, wfrag + 0 * 256 * 32, b_ui, WhA, NU_N);
    pull_item<<<pGrid, 256>>>(WhA, off + 0 * (NN + 1), esrc + 0 * NEDGE,
                              out + (size_t)NU_N * D);

    // etypes iu + uu: project, pull into user output half
    gemm_mma<<<gGrid, 256>>>(feat_item, wfrag + 1 * 256 * 32, b_iu, WhB, NI_N);
    gemm_mma<<<gGrid, 256>>>(feat_user, wfrag + 2 * 256 * 32, b_uu, WhA, NU_N);
    pull_user<<<pGrid, 256>>>(WhB, off + 1 * (NN + 1), esrc + 1 * NEDGE,
                              WhA, off + 2 * (NN + 1), esrc + 2 * NEDGE,
                              out);
}